// round 2
// baseline (speedup 1.0000x reference)
#include <cuda_runtime.h>
#include <cuda_bf16.h>

#define DIMV 33
#define DIM2 (DIMV*DIMV)        // 1089
#define DIM3 (DIMV*DIMV*DIMV)   // 35937
#define HW   (2048*2048)        // 4194304 = 2^22

// Channel-last repacked LUT: (b,g,r) -> float4(c0, c1, c2, 0)
// 35937 * 16B = 575 KB, lives in L2 after first touch.
__device__ float4 g_lut[DIM3];

__global__ void repack_lut_kernel(const float* __restrict__ lut) {
    int i = blockIdx.x * blockDim.x + threadIdx.x;
    if (i < DIM3) {
        g_lut[i] = make_float4(lut[i], lut[i + DIM3], lut[i + 2 * DIM3], 0.0f);
    }
}

__global__ void __launch_bounds__(256) lut3d_kernel(const float* __restrict__ x,
                                                    float* __restrict__ out) {
    // Each thread handles 4 consecutive pixels (float4 stream loads/stores).
    int t = blockIdx.x * 256 + threadIdx.x;
    int P = t * 4;                       // global pixel index (max 16.8M, fits int)
    int bimg = P >> 22;                  // batch index (HW = 2^22)
    int q    = P & (HW - 1);             // pixel within image, multiple of 4

    const float* xb = x + (size_t)bimg * 3 * HW + q;
    float4 rv = *(const float4*)(xb);
    float4 gv = *(const float4*)(xb + HW);
    float4 bv = *(const float4*)(xb + 2 * HW);

    float rr4[4] = {rv.x, rv.y, rv.z, rv.w};
    float gg4[4] = {gv.x, gv.y, gv.z, gv.w};
    float bb4[4] = {bv.x, bv.y, bv.z, bv.w};

    float o0[4], o1[4], o2[4];

    #pragma unroll
    for (int k = 0; k < 4; k++) {
        float rr = rr4[k] * 32.0f;
        float gg = gg4[k] * 32.0f;
        float bb = bb4[k] * 32.0f;

        int r0 = __float2int_rd(rr); r0 = min(max(r0, 0), 31);
        int g0 = __float2int_rd(gg); g0 = min(max(g0, 0), 31);
        int b0 = __float2int_rd(bb); b0 = min(max(b0, 0), 31);

        float fr = rr - (float)r0;
        float fg = gg - (float)g0;
        float fb = bb - (float)b0;

        int base = (b0 * DIMV + g0) * DIMV + r0;

        // 8 corner gathers, each fetching all 3 channels at once.
        float4 v000 = __ldg(&g_lut[base]);
        float4 v001 = __ldg(&g_lut[base + 1]);
        float4 v010 = __ldg(&g_lut[base + DIMV]);
        float4 v011 = __ldg(&g_lut[base + DIMV + 1]);
        float4 v100 = __ldg(&g_lut[base + DIM2]);
        float4 v101 = __ldg(&g_lut[base + DIM2 + 1]);
        float4 v110 = __ldg(&g_lut[base + DIM2 + DIMV]);
        float4 v111 = __ldg(&g_lut[base + DIM2 + DIMV + 1]);

        float fr0 = 1.0f - fr, fg0 = 1.0f - fg, fb0 = 1.0f - fb;

        float wb0g0 = fb0 * fg0;
        float wb0g1 = fb0 * fg;
        float wb1g0 = fb  * fg0;
        float wb1g1 = fb  * fg;

        float w000 = wb0g0 * fr0, w001 = wb0g0 * fr;
        float w010 = wb0g1 * fr0, w011 = wb0g1 * fr;
        float w100 = wb1g0 * fr0, w101 = wb1g0 * fr;
        float w110 = wb1g1 * fr0, w111 = wb1g1 * fr;

        float a0 = w000 * v000.x;
        float a1 = w000 * v000.y;
        float a2 = w000 * v000.z;
        a0 = fmaf(w001, v001.x, a0); a1 = fmaf(w001, v001.y, a1); a2 = fmaf(w001, v001.z, a2);
        a0 = fmaf(w010, v010.x, a0); a1 = fmaf(w010, v010.y, a1); a2 = fmaf(w010, v010.z, a2);
        a0 = fmaf(w011, v011.x, a0); a1 = fmaf(w011, v011.y, a1); a2 = fmaf(w011, v011.z, a2);
        a0 = fmaf(w100, v100.x, a0); a1 = fmaf(w100, v100.y, a1); a2 = fmaf(w100, v100.z, a2);
        a0 = fmaf(w101, v101.x, a0); a1 = fmaf(w101, v101.y, a1); a2 = fmaf(w101, v101.z, a2);
        a0 = fmaf(w110, v110.x, a0); a1 = fmaf(w110, v110.y, a1); a2 = fmaf(w110, v110.z, a2);
        a0 = fmaf(w111, v111.x, a0); a1 = fmaf(w111, v111.y, a1); a2 = fmaf(w111, v111.z, a2);

        o0[k] = a0;
        o1[k] = a1;
        o2[k] = a2;
    }

    float* ob = out + (size_t)bimg * 3 * HW + q;
    *(float4*)(ob)          = make_float4(o0[0], o0[1], o0[2], o0[3]);
    *(float4*)(ob + HW)     = make_float4(o1[0], o1[1], o1[2], o1[3]);
    *(float4*)(ob + 2 * HW) = make_float4(o2[0], o2[1], o2[2], o2[3]);
}

extern "C" void kernel_launch(void* const* d_in, const int* in_sizes, int n_in,
                              void* d_out, int out_size) {
    const float* x   = (const float*)d_in[0];   // (4, 3, 2048, 2048)
    const float* lut = (const float*)d_in[1];   // (3, 33, 33, 33)
    float* out = (float*)d_out;

    repack_lut_kernel<<<(DIM3 + 255) / 256, 256>>>(lut);

    int n_threads = (4 * HW) / 4;               // 4 pixels per thread
    lut3d_kernel<<<n_threads / 256, 256>>>(x, out);
}

// round 3
// speedup vs baseline: 2.7735x; 2.7735x over previous
#include <cuda_runtime.h>
#include <cuda_fp16.h>
#include <cuda_bf16.h>

#define DIMV 33
#define DIM2 (DIMV*DIMV)        // 1089
#define DIM3 (DIMV*DIMV*DIMV)   // 35937
#define HW   (2048*2048)        // 4194304 = 2^22

#define AB_BYTES   (DIM3 * 4)            // half2 per lattice point: 143748 B
#define C_WORDS    ((DIM3 + 1) / 2)      // half array copied as uint32: 17969 words
#define C_BYTES    (C_WORDS * 4)         // 71876 B (padded to even half count)
#define SMEM_BYTES (AB_BYTES + C_BYTES)  // 215624 B  (< 227 KB opt-in limit)

// Global staging for the fp16-compressed, channel-split LUT.
__device__ __half2 g_AB[DIM3];           // (c0, c1) per lattice point
__device__ __half  g_C [DIM3 + 1];       // c2 per lattice point (+pad for 4B copy)

__global__ void repack_lut_kernel(const float* __restrict__ lut) {
    int i = blockIdx.x * blockDim.x + threadIdx.x;
    if (i < DIM3) {
        g_AB[i] = __floats2half2_rn(lut[i], lut[i + DIM3]);
        g_C[i]  = __float2half_rn(lut[i + 2 * DIM3]);
    }
    if (i == 0) g_C[DIM3] = __float2half_rn(0.0f);
}

__global__ void __launch_bounds__(1024, 1)
lut3d_smem_kernel(const float* __restrict__ x, float* __restrict__ out, int nquads) {
    extern __shared__ char smem[];
    __half2* sAB = (__half2*)smem;
    __half*  sC  = (__half*)(smem + AB_BYTES);

    // Cooperative LUT copy into shared memory (4B granularity).
    {
        const unsigned* gab = (const unsigned*)g_AB;
        unsigned* dab = (unsigned*)sAB;
        for (int i = threadIdx.x; i < DIM3; i += blockDim.x) dab[i] = gab[i];
        const unsigned* gc = (const unsigned*)g_C;
        unsigned* dc = (unsigned*)sC;
        for (int i = threadIdx.x; i < C_WORDS; i += blockDim.x) dc[i] = gc[i];
    }
    __syncthreads();

    int stride = gridDim.x * blockDim.x;
    for (int t = blockIdx.x * blockDim.x + threadIdx.x; t < nquads; t += stride) {
        int P = t * 4;                    // global pixel index (quad start)
        int bimg = P >> 22;               // batch (HW = 2^22)
        int q    = P & (HW - 1);

        const float* xb = x + (size_t)bimg * 3 * HW + q;
        float4 rv = *(const float4*)(xb);
        float4 gv = *(const float4*)(xb + HW);
        float4 bv = *(const float4*)(xb + 2 * HW);

        float rr4[4] = {rv.x, rv.y, rv.z, rv.w};
        float gg4[4] = {gv.x, gv.y, gv.z, gv.w};
        float bb4[4] = {bv.x, bv.y, bv.z, bv.w};

        float o0[4], o1[4], o2[4];

        #pragma unroll
        for (int k = 0; k < 4; k++) {
            float rr = rr4[k] * 32.0f;
            float gg = gg4[k] * 32.0f;
            float bb = bb4[k] * 32.0f;

            int r0 = __float2int_rd(rr); r0 = min(max(r0, 0), 31);
            int g0 = __float2int_rd(gg); g0 = min(max(g0, 0), 31);
            int b0 = __float2int_rd(bb); b0 = min(max(b0, 0), 31);

            float fr = rr - (float)r0;
            float fg = gg - (float)g0;
            float fb = bb - (float)b0;

            int i000 = (b0 * DIMV + g0) * DIMV + r0;
            int i010 = i000 + DIMV;
            int i100 = i000 + DIM2;
            int i110 = i100 + DIMV;

            float2 v000 = __half22float2(sAB[i000]);
            float2 v001 = __half22float2(sAB[i000 + 1]);
            float2 v010 = __half22float2(sAB[i010]);
            float2 v011 = __half22float2(sAB[i010 + 1]);
            float2 v100 = __half22float2(sAB[i100]);
            float2 v101 = __half22float2(sAB[i100 + 1]);
            float2 v110 = __half22float2(sAB[i110]);
            float2 v111 = __half22float2(sAB[i110 + 1]);

            float c000 = __half2float(sC[i000]);
            float c001 = __half2float(sC[i000 + 1]);
            float c010 = __half2float(sC[i010]);
            float c011 = __half2float(sC[i010 + 1]);
            float c100 = __half2float(sC[i100]);
            float c101 = __half2float(sC[i100 + 1]);
            float c110 = __half2float(sC[i110]);
            float c111 = __half2float(sC[i110 + 1]);

            float fr0 = 1.0f - fr, fg0 = 1.0f - fg, fb0 = 1.0f - fb;

            float wb0g0 = fb0 * fg0;
            float wb0g1 = fb0 * fg;
            float wb1g0 = fb  * fg0;
            float wb1g1 = fb  * fg;

            float w000 = wb0g0 * fr0, w001 = wb0g0 * fr;
            float w010 = wb0g1 * fr0, w011 = wb0g1 * fr;
            float w100 = wb1g0 * fr0, w101 = wb1g0 * fr;
            float w110 = wb1g1 * fr0, w111 = wb1g1 * fr;

            float a0 = w000 * v000.x;
            float a1 = w000 * v000.y;
            float a2 = w000 * c000;
            a0 = fmaf(w001, v001.x, a0); a1 = fmaf(w001, v001.y, a1); a2 = fmaf(w001, c001, a2);
            a0 = fmaf(w010, v010.x, a0); a1 = fmaf(w010, v010.y, a1); a2 = fmaf(w010, c010, a2);
            a0 = fmaf(w011, v011.x, a0); a1 = fmaf(w011, v011.y, a1); a2 = fmaf(w011, c011, a2);
            a0 = fmaf(w100, v100.x, a0); a1 = fmaf(w100, v100.y, a1); a2 = fmaf(w100, c100, a2);
            a0 = fmaf(w101, v101.x, a0); a1 = fmaf(w101, v101.y, a1); a2 = fmaf(w101, c101, a2);
            a0 = fmaf(w110, v110.x, a0); a1 = fmaf(w110, v110.y, a1); a2 = fmaf(w110, c110, a2);
            a0 = fmaf(w111, v111.x, a0); a1 = fmaf(w111, v111.y, a1); a2 = fmaf(w111, c111, a2);

            o0[k] = a0;
            o1[k] = a1;
            o2[k] = a2;
        }

        float* ob = out + (size_t)bimg * 3 * HW + q;
        *(float4*)(ob)          = make_float4(o0[0], o0[1], o0[2], o0[3]);
        *(float4*)(ob + HW)     = make_float4(o1[0], o1[1], o1[2], o1[3]);
        *(float4*)(ob + 2 * HW) = make_float4(o2[0], o2[1], o2[2], o2[3]);
    }
}

extern "C" void kernel_launch(void* const* d_in, const int* in_sizes, int n_in,
                              void* d_out, int out_size) {
    const float* x   = (const float*)d_in[0];   // (4, 3, 2048, 2048)
    const float* lut = (const float*)d_in[1];   // (3, 33, 33, 33)
    float* out = (float*)d_out;

    cudaFuncSetAttribute(lut3d_smem_kernel,
                         cudaFuncAttributeMaxDynamicSharedMemorySize, SMEM_BYTES);

    repack_lut_kernel<<<(DIM3 + 255) / 256, 256>>>(lut);

    int nquads = (4 * HW) / 4;                  // 4 pixels per thread-iteration
    lut3d_smem_kernel<<<148, 1024, SMEM_BYTES>>>(x, out, nquads);
}